// round 2
// baseline (speedup 1.0000x reference)
#include <cuda_runtime.h>

#define NN   384
#define TS   32
#define NBLK 144          // 12x12 tiles of 32x32; < 148 SMs -> all co-resident

// Scratch (device globals: no allocation allowed)
__device__ float g_u[NN * NN];
__device__ float g_W[NN * NN];

// Software grid barrier state. gen increases monotonically across barriers and
// graph replays (sense-reversal via captured gen), count returns to 0 after
// every barrier -> deterministic for graph replay.
__device__ unsigned g_bar_count = 0;
__device__ unsigned g_bar_gen   = 0;

__device__ __forceinline__ void grid_barrier() {
    __syncthreads();
    if (threadIdx.x == 0 && threadIdx.y == 0) {
        __threadfence();                          // release: my block's writes
        unsigned gen = g_bar_gen;
        if (atomicAdd(&g_bar_count, 1) == NBLK - 1) {
            g_bar_count = 0;                      // reset before releasing
            __threadfence();
            atomicAdd(&g_bar_gen, 1);             // release everyone
        } else {
            while (*((volatile unsigned*)&g_bar_gen) == gen) { }
        }
        __threadfence();                          // acquire: others' writes
    }
    __syncthreads();
}

__device__ __forceinline__ float decode_lam(const void* p) {
    // lambda_param is a python scalar; dtype could be int32/int64/float32.
    int raw = *(const int*)p;
    unsigned ub = (unsigned)raw;
    if (ub < 0x01000000u) return (float)raw;      // small int bit pattern
    return __int_as_float(raw);                   // float32 bits
}

// One persistent kernel, three phases separated by grid barriers:
//   P1: u[i,j] = (adj>0 && i!=j) ? exp(-lam*dist) : 0
//   P2: S = u + offdiag(u@u);  W = (od>0 && i!=j && S>0) ? od/S : 0
//   P3: flows = u .* ( W + W@u^T + u^T@W )
__global__ __launch_bounds__(1024, 1)
void fused_kernel(const float* __restrict__ od,
                  const int*   __restrict__ adj,
                  const float* __restrict__ dist,
                  const void*  __restrict__ lam_p,
                  float*       __restrict__ out) {
    __shared__ float Ws[TS][TS];       // also used as As in phase 2
    __shared__ float Wc[TS][TS];       // also used as Bs in phase 2
    __shared__ float Ut[TS][TS + 1];
    __shared__ float Uc[TS][TS];

    const int tx = threadIdx.x, ty = threadIdx.y;
    const int tid = ty * TS + tx;
    const int tileX = blockIdx.x % (NN / TS);
    const int tileY = blockIdx.x / (NN / TS);
    const int rowBlk = tileY * TS;
    const int colBlk = tileX * TS;
    const int row = rowBlk + ty;
    const int col = colBlk + tx;

    // ---------------- Phase 1: build u ----------------
    {
        const float lam = decode_lam(lam_p);
        // 144 blocks * 1024 threads == NN*NN exactly: one element per thread
        int idx = blockIdx.x * 1024 + tid;
        int i = idx / NN;
        int j = idx - i * NN;
        float v = 0.f;
        if (adj[idx] > 0 && i != j) v = expf(-lam * dist[idx]);
        g_u[idx] = v;
    }
    grid_barrier();

    // ---------------- Phase 2: G = u@u, W epilogue ----------------
    {
        float acc = 0.f;
#pragma unroll 1
        for (int t = 0; t < NN / TS; ++t) {
            int p0 = t * TS;
            Ws[ty][tx] = g_u[row * NN + p0 + tx];          // A: u[row, p]
            Wc[ty][tx] = g_u[(p0 + ty) * NN + col];        // B: u[p, col]
            __syncthreads();
#pragma unroll
            for (int k = 0; k < TS; ++k)
                acc = fmaf(Ws[ty][k], Wc[k][tx], acc);
            __syncthreads();
        }
        int idx = row * NN + col;
        float uod = g_u[idx];
        float S = uod + ((row != col) ? acc : 0.f);
        float odv = od[idx];
        g_W[idx] = (odv > 0.f && row != col && S > 0.f) ? (odv / S) : 0.f;
    }
    grid_barrier();

    // ---------------- Phase 3: flows ----------------
    {
        float a1 = 0.f, a2 = 0.f;
#pragma unroll 1
        for (int t = 0; t < NN / TS; ++t) {
            int p0 = t * TS;
            Ws[ty][tx] = g_W[row * NN + p0 + tx];                // W[row, p]
            Ut[ty][tx] = g_u[(colBlk + ty) * NN + p0 + tx];      // u[colBlk+j, p]
            Uc[ty][tx] = g_u[(p0 + ty) * NN + rowBlk + tx];      // u[p, rowBlk+i]
            Wc[ty][tx] = g_W[(p0 + ty) * NN + colBlk + tx];      // W[p, colBlk+j]
            __syncthreads();
#pragma unroll
            for (int k = 0; k < TS; ++k) {
                a1 = fmaf(Ws[ty][k], Ut[tx][k], a1);             // (W u^T)[row,col]
                a2 = fmaf(Uc[k][ty], Wc[k][tx], a2);             // (u^T W)[row,col]
            }
            __syncthreads();
        }
        int idx = row * NN + col;
        out[idx] = g_u[idx] * (g_W[idx] + a1 + a2);
    }
}

extern "C" void kernel_launch(void* const* d_in, const int* in_sizes, int n_in,
                              void* d_out, int out_size) {
    const float* od   = (const float*)d_in[0];
    const int*   adj  = (const int*)d_in[1];
    const float* dist = (const float*)d_in[2];
    const void*  lamp = d_in[3];
    float* out = (float*)d_out;

    dim3 blk(TS, TS);
    fused_kernel<<<NBLK, blk>>>(od, adj, dist, lamp, out);
}

// round 3
// speedup vs baseline: 1.2600x; 1.2600x over previous
#include <cuda_runtime.h>

#define NN   384
#define TS   32
#define NT   (NN / TS)     // 12
#define NBLK (NT * NT)     // 144 blocks < 148 SMs -> co-resident, grid barrier safe

// Scratch (device globals: no allocation allowed)
__device__ float g_u[NN * NN];
__device__ float g_W[NN * NN];

// Software grid barrier (monotone gen; count resets -> graph-replay safe)
__device__ unsigned g_bar_count = 0;
__device__ unsigned g_bar_gen   = 0;

__device__ __forceinline__ void grid_barrier() {
    __syncthreads();
    if (threadIdx.x == 0 && threadIdx.y == 0) {
        __threadfence();
        unsigned gen = g_bar_gen;
        if (atomicAdd(&g_bar_count, 1) == NBLK - 1) {
            g_bar_count = 0;
            __threadfence();
            atomicAdd(&g_bar_gen, 1);
        } else {
            while (*((volatile unsigned*)&g_bar_gen) == gen) { }
        }
        __threadfence();
    }
    __syncthreads();
}

__device__ __forceinline__ float decode_lam(const void* p) {
    int raw = *(const int*)p;
    unsigned ub = (unsigned)raw;
    if (ub < 0x01000000u) return (float)raw;   // small-int bit pattern (int32/64)
    return __int_as_float(raw);                // float32 bits
}

// Phases:
//  P1: u = (adj>0 && i!=j) ? exp(-lam*dist) : 0
//  P2: W = od/S epilogue on S = u + offdiag(u@u)
//  P3: out = u .* (W + C),  C = [W | u^T] @ [u^T ; W]   (one K=768 GEMM)
__global__ __launch_bounds__(256, 1)
void fused_kernel(const float* __restrict__ od,
                  const int*   __restrict__ adj,
                  const float* __restrict__ dist,
                  const void*  __restrict__ lam_p,
                  float*       __restrict__ out) {
    // A stored transposed: Asm[k][r];  B natural: Bsm[k][c]. Pitch 34 keeps
    // float2 loads 8B-aligned and stores <=2-way conflicted.
    __shared__ __align__(16) float Asm[TS][TS + 2];
    __shared__ __align__(16) float Bsm[TS][TS + 2];

    const int tx = threadIdx.x, ty = threadIdx.y;     // 16x16
    const int tid  = ty * 16 + tx;
    const int lane = tid & 31;
    const int wrow = tid >> 5;                        // 0..7
    const int tileX = blockIdx.x % NT;
    const int tileY = blockIdx.x / NT;
    const int rowBlk = tileY * TS;
    const int colBlk = tileX * TS;

    // ---------------- Phase 1: build u (4 elems/thread, coalesced) ----------
    {
        const float lam = decode_lam(lam_p);
        int base = blockIdx.x * 1024 + tid;
#pragma unroll
        for (int i = 0; i < 4; ++i) {
            int idx = base + i * 256;
            int r = idx / NN, c = idx - r * NN;
            float v = 0.f;
            if (adj[idx] > 0 && r != c) v = expf(-lam * dist[idx]);
            g_u[idx] = v;
        }
    }
    grid_barrier();

    // ---------------- Phase 2: G = u@u, W epilogue (2x2 micro-tile) ---------
    {
        float acc00 = 0.f, acc01 = 0.f, acc10 = 0.f, acc11 = 0.f;
#pragma unroll 1
        for (int t = 0; t < NT; ++t) {
            int p0 = t * TS;
#pragma unroll
            for (int i = 0; i < 4; ++i) {
                int r = wrow + i * 8;
                Asm[lane][r] = g_u[(rowBlk + r) * NN + p0 + lane];   // A^T store
                Bsm[r][lane] = g_u[(p0 + r) * NN + colBlk + lane];   // natural
            }
            __syncthreads();
#pragma unroll
            for (int k = 0; k < TS; ++k) {
                float2 a = *(const float2*)&Asm[k][2 * ty];
                float2 b = *(const float2*)&Bsm[k][2 * tx];
                acc00 = fmaf(a.x, b.x, acc00);
                acc01 = fmaf(a.x, b.y, acc01);
                acc10 = fmaf(a.y, b.x, acc10);
                acc11 = fmaf(a.y, b.y, acc11);
            }
            __syncthreads();
        }
        float accs[2][2] = {{acc00, acc01}, {acc10, acc11}};
#pragma unroll
        for (int rr = 0; rr < 2; ++rr)
#pragma unroll
            for (int cc = 0; cc < 2; ++cc) {
                int r = rowBlk + 2 * ty + rr;
                int c = colBlk + 2 * tx + cc;
                int idx = r * NN + c;
                float S = g_u[idx] + ((r != c) ? accs[rr][cc] : 0.f);
                float odv = od[idx];
                g_W[idx] = (odv > 0.f && r != c && S > 0.f) ? (odv / S) : 0.f;
            }
    }
    grid_barrier();

    // ---------------- Phase 3: C = [W | u^T] @ [u^T ; W], fused epilogue ----
    {
        float acc00 = 0.f, acc01 = 0.f, acc10 = 0.f, acc11 = 0.f;
#pragma unroll 1
        for (int t = 0; t < 2 * NT; ++t) {
            if (t < NT) {
                int p0 = t * TS;
#pragma unroll
                for (int i = 0; i < 4; ++i) {
                    int r = wrow + i * 8;
                    // A' = W (row-major): Asm[k][r] = W[rowBlk+r][p0+k]
                    Asm[lane][r] = g_W[(rowBlk + r) * NN + p0 + lane];
                    // B' = u^T: Bsm[k][c] = u[colBlk+c][p0+k]
                    Bsm[lane][r] = g_u[(colBlk + r) * NN + p0 + lane];
                }
            } else {
                int p0 = (t - NT) * TS;
#pragma unroll
                for (int i = 0; i < 4; ++i) {
                    int k = wrow + i * 8;
                    // A' = u^T: Asm[k][r] = u[p0+k][rowBlk+r]
                    Asm[k][lane] = g_u[(p0 + k) * NN + rowBlk + lane];
                    // B' = W:  Bsm[k][c] = W[p0+k][colBlk+c]
                    Bsm[k][lane] = g_W[(p0 + k) * NN + colBlk + lane];
                }
            }
            __syncthreads();
#pragma unroll
            for (int k = 0; k < TS; ++k) {
                float2 a = *(const float2*)&Asm[k][2 * ty];
                float2 b = *(const float2*)&Bsm[k][2 * tx];
                acc00 = fmaf(a.x, b.x, acc00);
                acc01 = fmaf(a.x, b.y, acc01);
                acc10 = fmaf(a.y, b.x, acc10);
                acc11 = fmaf(a.y, b.y, acc11);
            }
            __syncthreads();
        }
        float accs[2][2] = {{acc00, acc01}, {acc10, acc11}};
#pragma unroll
        for (int rr = 0; rr < 2; ++rr) {
            int r = rowBlk + 2 * ty + rr;
            int c0 = colBlk + 2 * tx;
            int idx = r * NN + c0;
            float2 o;
            o.x = g_u[idx]     * (g_W[idx]     + accs[rr][0]);
            o.y = g_u[idx + 1] * (g_W[idx + 1] + accs[rr][1]);
            *(float2*)&out[idx] = o;
        }
    }
}

extern "C" void kernel_launch(void* const* d_in, const int* in_sizes, int n_in,
                              void* d_out, int out_size) {
    const float* od   = (const float*)d_in[0];
    const int*   adj  = (const int*)d_in[1];
    const float* dist = (const float*)d_in[2];
    const void*  lamp = d_in[3];
    float* out = (float*)d_out;

    dim3 blk(16, 16);
    fused_kernel<<<NBLK, blk>>>(od, adj, dist, lamp, out);
}

// round 4
// speedup vs baseline: 1.6275x; 1.2917x over previous
#include <cuda_runtime.h>

#define NN    384
#define TS    32
#define NT    (NN / TS)     // 12
#define NBLK  (NT * NT)     // 144 < 148 SMs -> co-resident, grid barrier safe
#define PITCH 34            // float2-aligned rows, <=2-way store conflicts

// Scratch (device globals: no allocation allowed)
__device__ __align__(16) float g_u[NN * NN];
__device__ __align__(16) float g_W[NN * NN];

// Software grid barrier (monotone gen, count resets -> graph-replay safe)
__device__ unsigned g_bar_count = 0;
__device__ unsigned g_bar_gen   = 0;

__device__ __forceinline__ void grid_barrier() {
    __syncthreads();
    if (threadIdx.x == 0) {
        __threadfence();
        unsigned gen = g_bar_gen;
        if (atomicAdd(&g_bar_count, 1) == NBLK - 1) {
            g_bar_count = 0;
            __threadfence();
            atomicAdd(&g_bar_gen, 1);
        } else {
            while (*(volatile unsigned*)&g_bar_gen == gen) { }
        }
        __threadfence();
    }
    __syncthreads();
}

__device__ __forceinline__ float decode_lam(const void* p) {
    int raw = *(const int*)p;
    unsigned ub = (unsigned)raw;
    if (ub < 0x01000000u) return (float)raw;   // small-int bits (int32/int64 low)
    return __int_as_float(raw);                // float32 bits
}

// P1: u = (adj>0 && i!=j) ? exp(-lam*dist) : 0
// P2: W = od/S on S = u + offdiag(u@u)
// P3: out = u .* (W + [W | u^T] @ [u^T ; W])    (single K=768 GEMM)
__global__ __launch_bounds__(256, 1)
void fused_kernel(const float* __restrict__ od,
                  const int*   __restrict__ adj,
                  const float* __restrict__ dist,
                  const void*  __restrict__ lam_p,
                  float*       __restrict__ out) {
    __shared__ __align__(16) float Asm[2][TS][PITCH];
    __shared__ __align__(16) float Bsm[2][TS][PITCH];

    const int tid = threadIdx.x;
    const int tx = tid & 15, ty = tid >> 4;     // compute map: 16x16, 2x2 micro
    const int lr = tid >> 3;                    // load map: row 0..31
    const int lq = tid & 7;                     // load map: col-quad 0..7
    const int tileX = blockIdx.x % NT;
    const int tileY = blockIdx.x / NT;
    const int rowBlk = tileY * TS;
    const int colBlk = tileX * TS;

    // ---------------- Phase 1: build u (float4/int4, 4 elems/thread) -------
    {
        const float lam = decode_lam(lam_p);
        int base = blockIdx.x * 1024 + tid * 4;
        int4   a4 = *(const int4*)&adj[base];
        float4 d4 = *(const float4*)&dist[base];
        int r = base / NN;                       // 4 consecutive cols, same row
        int c = base - r * NN;
        float4 v;
        v.x = (a4.x > 0 && r != c    ) ? expf(-lam * d4.x) : 0.f;
        v.y = (a4.y > 0 && r != c + 1) ? expf(-lam * d4.y) : 0.f;
        v.z = (a4.z > 0 && r != c + 2) ? expf(-lam * d4.z) : 0.f;
        v.w = (a4.w > 0 && r != c + 3) ? expf(-lam * d4.w) : 0.f;
        *(float4*)&g_u[base] = v;
    }
    grid_barrier();

    // ---------------- Phase 2: G = u@u, W epilogue --------------------------
    {
        float acc00 = 0.f, acc01 = 0.f, acc10 = 0.f, acc11 = 0.f;
        int buf = 0;
        // prefetch tile 0
        float4 aR = *(const float4*)&g_u[(rowBlk + lr) * NN + 4 * lq];
        float4 bR = *(const float4*)&g_u[lr * NN + colBlk + 4 * lq];
#pragma unroll 1
        for (int t = 0; t < NT; ++t) {
            // store regs -> smem[buf]  (A transposed, B natural)
            Asm[buf][4 * lq + 0][lr] = aR.x;
            Asm[buf][4 * lq + 1][lr] = aR.y;
            Asm[buf][4 * lq + 2][lr] = aR.z;
            Asm[buf][4 * lq + 3][lr] = aR.w;
            *(float2*)&Bsm[buf][lr][4 * lq]     = make_float2(bR.x, bR.y);
            *(float2*)&Bsm[buf][lr][4 * lq + 2] = make_float2(bR.z, bR.w);
            __syncthreads();
            if (t + 1 < NT) {                    // prefetch next tile (overlaps k-loop)
                int p0 = (t + 1) * TS;
                aR = *(const float4*)&g_u[(rowBlk + lr) * NN + p0 + 4 * lq];
                bR = *(const float4*)&g_u[(p0 + lr) * NN + colBlk + 4 * lq];
            }
#pragma unroll
            for (int k = 0; k < TS; ++k) {
                float2 a = *(const float2*)&Asm[buf][k][2 * ty];
                float2 b = *(const float2*)&Bsm[buf][k][2 * tx];
                acc00 = fmaf(a.x, b.x, acc00);
                acc01 = fmaf(a.x, b.y, acc01);
                acc10 = fmaf(a.y, b.x, acc10);
                acc11 = fmaf(a.y, b.y, acc11);
            }
            buf ^= 1;
        }
        float accs[2][2] = {{acc00, acc01}, {acc10, acc11}};
#pragma unroll
        for (int rr = 0; rr < 2; ++rr) {
            int r = rowBlk + 2 * ty + rr;
            int c0 = colBlk + 2 * tx;
            int idx = r * NN + c0;
            float2 uv  = *(const float2*)&g_u[idx];
            float2 odv = *(const float2*)&od[idx];
            float2 w2;
            float S0 = uv.x + ((r != c0)     ? accs[rr][0] : 0.f);
            float S1 = uv.y + ((r != c0 + 1) ? accs[rr][1] : 0.f);
            w2.x = (odv.x > 0.f && r != c0     && S0 > 0.f) ? (odv.x / S0) : 0.f;
            w2.y = (odv.y > 0.f && r != c0 + 1 && S1 > 0.f) ? (odv.y / S1) : 0.f;
            *(float2*)&g_W[idx] = w2;
        }
    }
    grid_barrier();

    // ---------------- Phase 3: C = [W | u^T] @ [u^T ; W] --------------------
    {
        float acc00 = 0.f, acc01 = 0.f, acc10 = 0.f, acc11 = 0.f;
        int buf = 0;
        // prefetch tile 0 (first half: A=W rows, B=u rows of colBlk -> both trans-store)
        float4 aR = *(const float4*)&g_W[(rowBlk + lr) * NN + 4 * lq];
        float4 bR = *(const float4*)&g_u[(colBlk + lr) * NN + 4 * lq];
#pragma unroll 1
        for (int t = 0; t < 2 * NT; ++t) {
            if (t < NT) {                        // both operands transposed-store
                Asm[buf][4 * lq + 0][lr] = aR.x;
                Asm[buf][4 * lq + 1][lr] = aR.y;
                Asm[buf][4 * lq + 2][lr] = aR.z;
                Asm[buf][4 * lq + 3][lr] = aR.w;
                Bsm[buf][4 * lq + 0][lr] = bR.x;
                Bsm[buf][4 * lq + 1][lr] = bR.y;
                Bsm[buf][4 * lq + 2][lr] = bR.z;
                Bsm[buf][4 * lq + 3][lr] = bR.w;
            } else {                             // both natural-store
                *(float2*)&Asm[buf][lr][4 * lq]     = make_float2(aR.x, aR.y);
                *(float2*)&Asm[buf][lr][4 * lq + 2] = make_float2(aR.z, aR.w);
                *(float2*)&Bsm[buf][lr][4 * lq]     = make_float2(bR.x, bR.y);
                *(float2*)&Bsm[buf][lr][4 * lq + 2] = make_float2(bR.z, bR.w);
            }
            __syncthreads();
            int tn = t + 1;
            if (tn < 2 * NT) {                   // prefetch next (overlaps k-loop)
                if (tn < NT) {
                    int p0 = tn * TS;
                    aR = *(const float4*)&g_W[(rowBlk + lr) * NN + p0 + 4 * lq];
                    bR = *(const float4*)&g_u[(colBlk + lr) * NN + p0 + 4 * lq];
                } else {
                    int p0 = (tn - NT) * TS;
                    aR = *(const float4*)&g_u[(p0 + lr) * NN + rowBlk + 4 * lq];
                    bR = *(const float4*)&g_W[(p0 + lr) * NN + colBlk + 4 * lq];
                }
            }
#pragma unroll
            for (int k = 0; k < TS; ++k) {
                float2 a = *(const float2*)&Asm[buf][k][2 * ty];
                float2 b = *(const float2*)&Bsm[buf][k][2 * tx];
                acc00 = fmaf(a.x, b.x, acc00);
                acc01 = fmaf(a.x, b.y, acc01);
                acc10 = fmaf(a.y, b.x, acc10);
                acc11 = fmaf(a.y, b.y, acc11);
            }
            buf ^= 1;
        }
        float accs[2][2] = {{acc00, acc01}, {acc10, acc11}};
#pragma unroll
        for (int rr = 0; rr < 2; ++rr) {
            int r = rowBlk + 2 * ty + rr;
            int c0 = colBlk + 2 * tx;
            int idx = r * NN + c0;
            float2 uv = *(const float2*)&g_u[idx];
            float2 wv = *(const float2*)&g_W[idx];
            float2 o;
            o.x = uv.x * (wv.x + accs[rr][0]);
            o.y = uv.y * (wv.y + accs[rr][1]);
            *(float2*)&out[idx] = o;
        }
    }
}

extern "C" void kernel_launch(void* const* d_in, const int* in_sizes, int n_in,
                              void* d_out, int out_size) {
    const float* od   = (const float*)d_in[0];
    const int*   adj  = (const int*)d_in[1];
    const float* dist = (const float*)d_in[2];
    const void*  lamp = d_in[3];
    float* out = (float*)d_out;

    fused_kernel<<<NBLK, 256>>>(od, adj, dist, lamp, out);
}

// round 6
// speedup vs baseline: 1.7025x; 1.0461x over previous
#include <cuda_runtime.h>

#define NN    384
#define TS    32
#define NT    (NN / TS)     // 12
#define NBLK  (NT * NT)     // 144 < 148 SMs -> co-resident, grid barrier safe
#define PITCH 34

// Scratch (device globals: no allocation allowed)
__device__ __align__(16) float g_u[NN * NN];
__device__ __align__(16) float g_W[NN * NN];

// Software grid barrier (monotone gen, count resets -> graph-replay safe)
__device__ unsigned g_bar_count = 0;
__device__ unsigned g_bar_gen   = 0;

__device__ __forceinline__ void grid_barrier() {
    __syncthreads();
    if (threadIdx.x == 0) {
        __threadfence();
        unsigned gen = g_bar_gen;
        if (atomicAdd(&g_bar_count, 1) == NBLK - 1) {
            g_bar_count = 0;
            __threadfence();
            atomicAdd(&g_bar_gen, 1);
        } else {
            while (*(volatile unsigned*)&g_bar_gen == gen) { }
        }
        __threadfence();
    }
    __syncthreads();
}

__device__ __forceinline__ void group_barrier(int g) {
    asm volatile("bar.sync %0, 256;" :: "r"(1 + g) : "memory");
}

__device__ __forceinline__ float decode_lam(const void* p) {
    int raw = *(const int*)p;
    unsigned ub = (unsigned)raw;
    if (ub < 0x01000000u) return (float)raw;   // small-int bits (int32/int64 low)
    return __int_as_float(raw);                // float32 bits
}

// P1: u = (adj>0 && i!=j) ? exp(-lam*dist) : 0
// P2: W = od/S on S = u + offdiag(u@u)
// P3: out = u .* (W + [W | u^T] @ [u^T ; W])    (single K=768 GEMM)
// K is split across 2 warp-groups of 256 threads; partial accs reduced in smem.
__global__ __launch_bounds__(512, 1)
void fused_kernel(const float* __restrict__ od,
                  const int*   __restrict__ adj,
                  const float* __restrict__ dist,
                  const void*  __restrict__ lam_p,
                  float*       __restrict__ out) {
    __shared__ __align__(16) float Asm[2][2][TS][PITCH];   // [group][buf]
    __shared__ __align__(16) float Bsm[2][2][TS][PITCH];

    const int tid  = threadIdx.x;
    const int g    = tid >> 8;                 // warp-group 0/1
    const int gtid = tid & 255;
    const int tx = gtid & 15, ty = gtid >> 4;  // 16x16 compute map, 2x2 micro
    const int lr = gtid >> 3;                  // load row 0..31
    const int lq = gtid & 7;                   // load col-quad 0..7
    const int tileX = blockIdx.x % NT;
    const int tileY = blockIdx.x / NT;
    const int rowBlk = tileY * TS;
    const int colBlk = tileX * TS;
    float* red = &Asm[0][0][0][0];             // 4KB reduction scratch (reused)

    // ---------------- Phase 1: build u (float2/int2, 2 elems/thread) -------
    {
        const float lam = decode_lam(lam_p);
        int base = blockIdx.x * 1024 + tid * 2;
        int2   a2 = *(const int2*)&adj[base];
        float2 d2 = *(const float2*)&dist[base];
        int r = base / NN;                     // same row (NN even)
        int c = base - r * NN;
        float2 v;
        v.x = (a2.x > 0 && r != c    ) ? expf(-lam * d2.x) : 0.f;
        v.y = (a2.y > 0 && r != c + 1) ? expf(-lam * d2.y) : 0.f;
        *(float2*)&g_u[base] = v;
    }
    grid_barrier();

    // ---------------- Phase 2: G = u@u, W epilogue --------------------------
    {
        float acc00 = 0.f, acc01 = 0.f, acc10 = 0.f, acc11 = 0.f;
        int buf = 0;
        const int tb = g * (NT / 2);           // this group's first k-tile
        float4 aR = *(const float4*)&g_u[(rowBlk + lr) * NN + tb * TS + 4 * lq];
        float4 bR = *(const float4*)&g_u[(tb * TS + lr) * NN + colBlk + 4 * lq];
#pragma unroll 1
        for (int t = 0; t < NT / 2; ++t) {
            Asm[g][buf][4 * lq + 0][lr] = aR.x;               // A transposed
            Asm[g][buf][4 * lq + 1][lr] = aR.y;
            Asm[g][buf][4 * lq + 2][lr] = aR.z;
            Asm[g][buf][4 * lq + 3][lr] = aR.w;
            *(float2*)&Bsm[g][buf][lr][4 * lq]     = make_float2(bR.x, bR.y);
            *(float2*)&Bsm[g][buf][lr][4 * lq + 2] = make_float2(bR.z, bR.w);
            group_barrier(g);
            if (t + 1 < NT / 2) {
                int p0 = (tb + t + 1) * TS;
                aR = *(const float4*)&g_u[(rowBlk + lr) * NN + p0 + 4 * lq];
                bR = *(const float4*)&g_u[(p0 + lr) * NN + colBlk + 4 * lq];
            }
#pragma unroll
            for (int k = 0; k < TS; ++k) {
                float2 a = *(const float2*)&Asm[g][buf][k][2 * ty];
                float2 b = *(const float2*)&Bsm[g][buf][k][2 * tx];
                acc00 = fmaf(a.x, b.x, acc00);
                acc01 = fmaf(a.x, b.y, acc01);
                acc10 = fmaf(a.y, b.x, acc10);
                acc11 = fmaf(a.y, b.y, acc11);
            }
            buf ^= 1;
        }
        __syncthreads();
        if (g == 1) {
            float4 v = make_float4(acc00, acc01, acc10, acc11);
            *(float4*)&red[gtid * 4] = v;
        }
        __syncthreads();
        if (g == 0) {
            float4 v = *(const float4*)&red[gtid * 4];
            acc00 += v.x; acc01 += v.y; acc10 += v.z; acc11 += v.w;
            float accs[2][2] = {{acc00, acc01}, {acc10, acc11}};
#pragma unroll
            for (int rr = 0; rr < 2; ++rr) {
                int r = rowBlk + 2 * ty + rr;
                int c0 = colBlk + 2 * tx;
                int idx = r * NN + c0;
                float2 uv  = *(const float2*)&g_u[idx];
                float2 odv = *(const float2*)&od[idx];
                float S0 = uv.x + ((r != c0)     ? accs[rr][0] : 0.f);
                float S1 = uv.y + ((r != c0 + 1) ? accs[rr][1] : 0.f);
                float2 w2;
                w2.x = (odv.x > 0.f && r != c0     && S0 > 0.f) ? (odv.x / S0) : 0.f;
                w2.y = (odv.y > 0.f && r != c0 + 1 && S1 > 0.f) ? (odv.y / S1) : 0.f;
                *(float2*)&g_W[idx] = w2;
            }
        }
    }
    grid_barrier();

    // ---------------- Phase 3: C = [W | u^T] @ [u^T ; W] --------------------
    // Group 0: first half (A=W rows, B=u rows of colBlk; both transposed-store)
    // Group 1: second half (A=u^T, B=W; both natural-store)
    {
        float acc00 = 0.f, acc01 = 0.f, acc10 = 0.f, acc11 = 0.f;
        int buf = 0;
        float4 aR, bR;
        if (g == 0) {
            aR = *(const float4*)&g_W[(rowBlk + lr) * NN + 4 * lq];
            bR = *(const float4*)&g_u[(colBlk + lr) * NN + 4 * lq];
        } else {
            aR = *(const float4*)&g_u[lr * NN + rowBlk + 4 * lq];
            bR = *(const float4*)&g_W[lr * NN + colBlk + 4 * lq];
        }
#pragma unroll 1
        for (int t = 0; t < NT; ++t) {
            if (g == 0) {                                     // transposed stores
                Asm[0][buf][4 * lq + 0][lr] = aR.x;
                Asm[0][buf][4 * lq + 1][lr] = aR.y;
                Asm[0][buf][4 * lq + 2][lr] = aR.z;
                Asm[0][buf][4 * lq + 3][lr] = aR.w;
                Bsm[0][buf][4 * lq + 0][lr] = bR.x;
                Bsm[0][buf][4 * lq + 1][lr] = bR.y;
                Bsm[0][buf][4 * lq + 2][lr] = bR.z;
                Bsm[0][buf][4 * lq + 3][lr] = bR.w;
            } else {                                          // natural stores
                *(float2*)&Asm[1][buf][lr][4 * lq]     = make_float2(aR.x, aR.y);
                *(float2*)&Asm[1][buf][lr][4 * lq + 2] = make_float2(aR.z, aR.w);
                *(float2*)&Bsm[1][buf][lr][4 * lq]     = make_float2(bR.x, bR.y);
                *(float2*)&Bsm[1][buf][lr][4 * lq + 2] = make_float2(bR.z, bR.w);
            }
            group_barrier(g);
            if (t + 1 < NT) {
                int p0 = (t + 1) * TS;
                if (g == 0) {
                    aR = *(const float4*)&g_W[(rowBlk + lr) * NN + p0 + 4 * lq];
                    bR = *(const float4*)&g_u[(colBlk + lr) * NN + p0 + 4 * lq];
                } else {
                    aR = *(const float4*)&g_u[(p0 + lr) * NN + rowBlk + 4 * lq];
                    bR = *(const float4*)&g_W[(p0 + lr) * NN + colBlk + 4 * lq];
                }
            }
#pragma unroll
            for (int k = 0; k < TS; ++k) {
                float2 a = *(const float2*)&Asm[g][buf][k][2 * ty];
                float2 b = *(const float2*)&Bsm[g][buf][k][2 * tx];
                acc00 = fmaf(a.x, b.x, acc00);
                acc01 = fmaf(a.x, b.y, acc01);
                acc10 = fmaf(a.y, b.x, acc10);
                acc11 = fmaf(a.y, b.y, acc11);
            }
            buf ^= 1;
        }
        __syncthreads();
        if (g == 1) {
            float4 v = make_float4(acc00, acc01, acc10, acc11);
            *(float4*)&red[gtid * 4] = v;
        }
        __syncthreads();
        if (g == 0) {
            float4 v = *(const float4*)&red[gtid * 4];
            acc00 += v.x; acc01 += v.y; acc10 += v.z; acc11 += v.w;
            float accs[2][2] = {{acc00, acc01}, {acc10, acc11}};
#pragma unroll
            for (int rr = 0; rr < 2; ++rr) {
                int r = rowBlk + 2 * ty + rr;
                int c0 = colBlk + 2 * tx;
                int idx = r * NN + c0;
                float2 uv = *(const float2*)&g_u[idx];
                float2 wv = *(const float2*)&g_W[idx];
                float2 o;
                o.x = uv.x * (wv.x + accs[rr][0]);
                o.y = uv.y * (wv.y + accs[rr][1]);
                *(float2*)&out[idx] = o;
            }
        }
    }
}

extern "C" void kernel_launch(void* const* d_in, const int* in_sizes, int n_in,
                              void* d_out, int out_size) {
    const float* od   = (const float*)d_in[0];
    const int*   adj  = (const int*)d_in[1];
    const float* dist = (const float*)d_in[2];
    const void*  lamp = d_in[3];
    float* out = (float*)d_out;

    fused_kernel<<<NBLK, 512>>>(od, adj, dist, lamp, out);
}

// round 7
// speedup vs baseline: 1.8162x; 1.0667x over previous
#include <cuda_runtime.h>

#define NN    384
#define TS    32
#define NT    (NN / TS)     // 12
#define NBLK  (NT * NT)     // 144 < 148 SMs -> co-resident, grid barrier safe
#define PA    36            // A pitch: float4-aligned rows (144B)
#define PB    34            // B pitch: float2-aligned rows

// Scratch (device globals: no allocation allowed)
__device__ __align__(16) float g_u[NN * NN];
__device__ __align__(16) float g_W[NN * NN];

// Software grid barrier (monotone gen, count resets -> graph-replay safe)
__device__ unsigned g_bar_count = 0;
__device__ unsigned g_bar_gen   = 0;

__device__ __forceinline__ void grid_barrier() {
    __syncthreads();
    if (threadIdx.x == 0) {
        __threadfence();
        unsigned gen = g_bar_gen;
        if (atomicAdd(&g_bar_count, 1) == NBLK - 1) {
            g_bar_count = 0;
            __threadfence();
            atomicAdd(&g_bar_gen, 1);
        } else {
            while (*(volatile unsigned*)&g_bar_gen == gen) { }
        }
        __threadfence();
    }
    __syncthreads();
}

__device__ __forceinline__ void group_barrier(int g) {
    asm volatile("bar.sync %0, 128;" :: "r"(1 + g) : "memory");
}

__device__ __forceinline__ float decode_lam(const void* p) {
    int raw = *(const int*)p;
    unsigned ub = (unsigned)raw;
    if (ub < 0x01000000u) return (float)raw;   // small-int bits (int32/int64 low)
    return __int_as_float(raw);                // float32 bits
}

// P1: u = (adj>0 && i!=j) ? exp(-lam*dist) : 0
// P2: W = od/S on S = u + offdiag(u@u)
// P3: out = u .* (W + [W | u^T] @ [u^T ; W])   (single K=768 GEMM)
// 4 warp-groups of 128 threads split K; 4x2 register micro-tile per thread.
__global__ __launch_bounds__(512, 1)
void fused_kernel(const float* __restrict__ od,
                  const int*   __restrict__ adj,
                  const float* __restrict__ dist,
                  const void*  __restrict__ lam_p,
                  float*       __restrict__ out) {
    __shared__ __align__(16) float Asm[4][TS][PA];   // [group][k][row], A^T
    __shared__ __align__(16) float Bsm[4][TS][PB];   // [group][k][col]

    const int tid  = threadIdx.x;
    const int g    = tid >> 7;                 // group 0..3
    const int gtid = tid & 127;
    const int tyy = gtid >> 4;                 // 0..7  -> rows 4*tyy..+3
    const int txx = gtid & 15;                 // 0..15 -> cols 2*txx..+1
    const int lr = gtid >> 3;                  // load rows lr, lr+16
    const int lq = gtid & 7;                   // load col-quad
    const int tileX = blockIdx.x % NT;
    const int tileY = blockIdx.x / NT;
    const int rowBlk = tileY * TS;
    const int colBlk = tileX * TS;
    float* red = &Asm[0][0][0];                // reduction scratch (12KB needed)

    // ---------------- Phase 1: build u (2 elems/thread) ---------------------
    {
        const float lam = decode_lam(lam_p);
        int base = blockIdx.x * 1024 + tid * 2;
        int2   a2 = *(const int2*)&adj[base];
        float2 d2 = *(const float2*)&dist[base];
        int r = base / NN;
        int c = base - r * NN;
        float2 v;
        v.x = (a2.x > 0 && r != c    ) ? expf(-lam * d2.x) : 0.f;
        v.y = (a2.y > 0 && r != c + 1) ? expf(-lam * d2.y) : 0.f;
        *(float2*)&g_u[base] = v;
    }
    grid_barrier();

    // ---------------- Phase 2: G = u@u, W epilogue --------------------------
    {
        float acc[4][2] = {};
        const int tb = g * 3;                  // 3 k-tiles per group
        int p0 = tb * TS;
        float4 aR0 = *(const float4*)&g_u[(rowBlk + lr) * NN + p0 + 4 * lq];
        float4 aR1 = *(const float4*)&g_u[(rowBlk + lr + 16) * NN + p0 + 4 * lq];
        float4 bR0 = *(const float4*)&g_u[(p0 + lr) * NN + colBlk + 4 * lq];
        float4 bR1 = *(const float4*)&g_u[(p0 + lr + 16) * NN + colBlk + 4 * lq];
#pragma unroll 1
        for (int t = 0; t < 3; ++t) {
            // A transposed store
            Asm[g][4 * lq + 0][lr] = aR0.x;  Asm[g][4 * lq + 0][lr + 16] = aR1.x;
            Asm[g][4 * lq + 1][lr] = aR0.y;  Asm[g][4 * lq + 1][lr + 16] = aR1.y;
            Asm[g][4 * lq + 2][lr] = aR0.z;  Asm[g][4 * lq + 2][lr + 16] = aR1.z;
            Asm[g][4 * lq + 3][lr] = aR0.w;  Asm[g][4 * lq + 3][lr + 16] = aR1.w;
            // B natural store
            *(float2*)&Bsm[g][lr][4 * lq]          = make_float2(bR0.x, bR0.y);
            *(float2*)&Bsm[g][lr][4 * lq + 2]      = make_float2(bR0.z, bR0.w);
            *(float2*)&Bsm[g][lr + 16][4 * lq]     = make_float2(bR1.x, bR1.y);
            *(float2*)&Bsm[g][lr + 16][4 * lq + 2] = make_float2(bR1.z, bR1.w);
            group_barrier(g);
            if (t + 1 < 3) {
                int pn = (tb + t + 1) * TS;
                aR0 = *(const float4*)&g_u[(rowBlk + lr) * NN + pn + 4 * lq];
                aR1 = *(const float4*)&g_u[(rowBlk + lr + 16) * NN + pn + 4 * lq];
                bR0 = *(const float4*)&g_u[(pn + lr) * NN + colBlk + 4 * lq];
                bR1 = *(const float4*)&g_u[(pn + lr + 16) * NN + colBlk + 4 * lq];
            }
#pragma unroll
            for (int k = 0; k < TS; ++k) {
                float4 a = *(const float4*)&Asm[g][k][4 * tyy];
                float2 b = *(const float2*)&Bsm[g][k][2 * txx];
                acc[0][0] = fmaf(a.x, b.x, acc[0][0]);
                acc[0][1] = fmaf(a.x, b.y, acc[0][1]);
                acc[1][0] = fmaf(a.y, b.x, acc[1][0]);
                acc[1][1] = fmaf(a.y, b.y, acc[1][1]);
                acc[2][0] = fmaf(a.z, b.x, acc[2][0]);
                acc[2][1] = fmaf(a.z, b.y, acc[2][1]);
                acc[3][0] = fmaf(a.w, b.x, acc[3][0]);
                acc[3][1] = fmaf(a.w, b.y, acc[3][1]);
            }
            group_barrier(g);
        }
        __syncthreads();
        if (g > 0) {
            float* dst = &red[((g - 1) * 128 + gtid) * 8];
            *(float4*)&dst[0] = make_float4(acc[0][0], acc[0][1], acc[1][0], acc[1][1]);
            *(float4*)&dst[4] = make_float4(acc[2][0], acc[2][1], acc[3][0], acc[3][1]);
        }
        __syncthreads();
        if (g == 0) {
#pragma unroll
            for (int gg = 0; gg < 3; ++gg) {
                const float* src = &red[(gg * 128 + gtid) * 8];
                float4 lo = *(const float4*)&src[0];
                float4 hi = *(const float4*)&src[4];
                acc[0][0] += lo.x; acc[0][1] += lo.y; acc[1][0] += lo.z; acc[1][1] += lo.w;
                acc[2][0] += hi.x; acc[2][1] += hi.y; acc[3][0] += hi.z; acc[3][1] += hi.w;
            }
#pragma unroll
            for (int rr = 0; rr < 4; ++rr) {
                int r = rowBlk + 4 * tyy + rr;
                int c0 = colBlk + 2 * txx;
                int idx = r * NN + c0;
                float2 uv  = *(const float2*)&g_u[idx];
                float2 odv = *(const float2*)&od[idx];
                float S0 = uv.x + ((r != c0)     ? acc[rr][0] : 0.f);
                float S1 = uv.y + ((r != c0 + 1) ? acc[rr][1] : 0.f);
                float2 w2;
                w2.x = (odv.x > 0.f && r != c0     && S0 > 0.f) ? (odv.x / S0) : 0.f;
                w2.y = (odv.y > 0.f && r != c0 + 1 && S1 > 0.f) ? (odv.y / S1) : 0.f;
                *(float2*)&g_W[idx] = w2;
            }
        }
    }
    grid_barrier();

    // ---------------- Phase 3: C = [W | u^T] @ [u^T ; W] --------------------
    // Groups 0,1: first half (A=W rows, B=u rows of colBlk; both transposed-store)
    // Groups 2,3: second half (A=u^T, B=W; both natural-store)
    {
        float acc[4][2] = {};
        const int first = (g < 2);
        const int tb = first ? g * 6 : (g - 2) * 6 + 6;   // unused base helper
        (void)tb;
        float4 aR0, aR1, bR0, bR1;
        {
            int vt = g * 6;
            int p0 = first ? vt * TS : (vt - 12) * TS;
            if (first) {
                aR0 = *(const float4*)&g_W[(rowBlk + lr) * NN + p0 + 4 * lq];
                aR1 = *(const float4*)&g_W[(rowBlk + lr + 16) * NN + p0 + 4 * lq];
                bR0 = *(const float4*)&g_u[(colBlk + lr) * NN + p0 + 4 * lq];
                bR1 = *(const float4*)&g_u[(colBlk + lr + 16) * NN + p0 + 4 * lq];
            } else {
                aR0 = *(const float4*)&g_u[(p0 + lr) * NN + rowBlk + 4 * lq];
                aR1 = *(const float4*)&g_u[(p0 + lr + 16) * NN + rowBlk + 4 * lq];
                bR0 = *(const float4*)&g_W[(p0 + lr) * NN + colBlk + 4 * lq];
                bR1 = *(const float4*)&g_W[(p0 + lr + 16) * NN + colBlk + 4 * lq];
            }
        }
#pragma unroll 1
        for (int t = 0; t < 6; ++t) {
            if (first) {                       // transposed stores (A and B)
                Asm[g][4 * lq + 0][lr] = aR0.x;  Asm[g][4 * lq + 0][lr + 16] = aR1.x;
                Asm[g][4 * lq + 1][lr] = aR0.y;  Asm[g][4 * lq + 1][lr + 16] = aR1.y;
                Asm[g][4 * lq + 2][lr] = aR0.z;  Asm[g][4 * lq + 2][lr + 16] = aR1.z;
                Asm[g][4 * lq + 3][lr] = aR0.w;  Asm[g][4 * lq + 3][lr + 16] = aR1.w;
                Bsm[g][4 * lq + 0][lr] = bR0.x;  Bsm[g][4 * lq + 0][lr + 16] = bR1.x;
                Bsm[g][4 * lq + 1][lr] = bR0.y;  Bsm[g][4 * lq + 1][lr + 16] = bR1.y;
                Bsm[g][4 * lq + 2][lr] = bR0.z;  Bsm[g][4 * lq + 2][lr + 16] = bR1.z;
                Bsm[g][4 * lq + 3][lr] = bR0.w;  Bsm[g][4 * lq + 3][lr + 16] = bR1.w;
            } else {                           // natural stores (A and B)
                *(float2*)&Asm[g][lr][4 * lq]          = make_float2(aR0.x, aR0.y);
                *(float2*)&Asm[g][lr][4 * lq + 2]      = make_float2(aR0.z, aR0.w);
                *(float2*)&Asm[g][lr + 16][4 * lq]     = make_float2(aR1.x, aR1.y);
                *(float2*)&Asm[g][lr + 16][4 * lq + 2] = make_float2(aR1.z, aR1.w);
                *(float2*)&Bsm[g][lr][4 * lq]          = make_float2(bR0.x, bR0.y);
                *(float2*)&Bsm[g][lr][4 * lq + 2]      = make_float2(bR0.z, bR0.w);
                *(float2*)&Bsm[g][lr + 16][4 * lq]     = make_float2(bR1.x, bR1.y);
                *(float2*)&Bsm[g][lr + 16][4 * lq + 2] = make_float2(bR1.z, bR1.w);
            }
            group_barrier(g);
            if (t + 1 < 6) {
                int vt = g * 6 + t + 1;
                int p0 = first ? vt * TS : (vt - 12) * TS;
                if (first) {
                    aR0 = *(const float4*)&g_W[(rowBlk + lr) * NN + p0 + 4 * lq];
                    aR1 = *(const float4*)&g_W[(rowBlk + lr + 16) * NN + p0 + 4 * lq];
                    bR0 = *(const float4*)&g_u[(colBlk + lr) * NN + p0 + 4 * lq];
                    bR1 = *(const float4*)&g_u[(colBlk + lr + 16) * NN + p0 + 4 * lq];
                } else {
                    aR0 = *(const float4*)&g_u[(p0 + lr) * NN + rowBlk + 4 * lq];
                    aR1 = *(const float4*)&g_u[(p0 + lr + 16) * NN + rowBlk + 4 * lq];
                    bR0 = *(const float4*)&g_W[(p0 + lr) * NN + colBlk + 4 * lq];
                    bR1 = *(const float4*)&g_W[(p0 + lr + 16) * NN + colBlk + 4 * lq];
                }
            }
#pragma unroll
            for (int k = 0; k < TS; ++k) {
                float4 a = *(const float4*)&Asm[g][k][4 * tyy];
                float2 b = *(const float2*)&Bsm[g][k][2 * txx];
                acc[0][0] = fmaf(a.x, b.x, acc[0][0]);
                acc[0][1] = fmaf(a.x, b.y, acc[0][1]);
                acc[1][0] = fmaf(a.y, b.x, acc[1][0]);
                acc[1][1] = fmaf(a.y, b.y, acc[1][1]);
                acc[2][0] = fmaf(a.z, b.x, acc[2][0]);
                acc[2][1] = fmaf(a.z, b.y, acc[2][1]);
                acc[3][0] = fmaf(a.w, b.x, acc[3][0]);
                acc[3][1] = fmaf(a.w, b.y, acc[3][1]);
            }
            group_barrier(g);
        }
        __syncthreads();
        if (g > 0) {
            float* dst = &red[((g - 1) * 128 + gtid) * 8];
            *(float4*)&dst[0] = make_float4(acc[0][0], acc[0][1], acc[1][0], acc[1][1]);
            *(float4*)&dst[4] = make_float4(acc[2][0], acc[2][1], acc[3][0], acc[3][1]);
        }
        __syncthreads();
        if (g == 0) {
#pragma unroll
            for (int gg = 0; gg < 3; ++gg) {
                const float* src = &red[(gg * 128 + gtid) * 8];
                float4 lo = *(const float4*)&src[0];
                float4 hi = *(const float4*)&src[4];
                acc[0][0] += lo.x; acc[0][1] += lo.y; acc[1][0] += lo.z; acc[1][1] += lo.w;
                acc[2][0] += hi.x; acc[2][1] += hi.y; acc[3][0] += hi.z; acc[3][1] += hi.w;
            }
#pragma unroll
            for (int rr = 0; rr < 4; ++rr) {
                int r = rowBlk + 4 * tyy + rr;
                int c0 = colBlk + 2 * txx;
                int idx = r * NN + c0;
                float2 uv = *(const float2*)&g_u[idx];
                float2 wv = *(const float2*)&g_W[idx];
                float2 o;
                o.x = uv.x * (wv.x + acc[rr][0]);
                o.y = uv.y * (wv.y + acc[rr][1]);
                *(float2*)&out[idx] = o;
            }
        }
    }
}

extern "C" void kernel_launch(void* const* d_in, const int* in_sizes, int n_in,
                              void* d_out, int out_size) {
    const float* od   = (const float*)d_in[0];
    const int*   adj  = (const int*)d_in[1];
    const float* dist = (const float*)d_in[2];
    const void*  lamp = d_in[3];
    float* out = (float*)d_out;

    fused_kernel<<<NBLK, 512>>>(od, adj, dist, lamp, out);
}

// round 8
// speedup vs baseline: 1.9783x; 1.0893x over previous
#include <cuda_runtime.h>

#define NN    384
#define TS    32
#define NT    (NN / TS)     // 12
#define NBLK  (NT * NT)     // 144 < 148 SMs -> co-resident, grid barrier safe
#define PA    36            // A pitch: float4-aligned rows
#define PB    34            // B pitch: float2-aligned rows

// Scratch (device globals: no allocation allowed)
__device__ __align__(16) float g_u[NN * NN];
__device__ __align__(16) float g_W[NN * NN];

// Distributed grid barrier state: per-block flags + one release word.
// Strictly monotone across barriers AND graph replays -> deterministic.
__device__ unsigned g_flags[NBLK];
__device__ unsigned g_gen;

__device__ __forceinline__ void grid_barrier(unsigned epoch) {
    __syncthreads();
    if (blockIdx.x == 0) {
        int t = threadIdx.x;
        if (t >= 1 && t < NBLK) {                    // parallel scan of arrivals
            while (*(volatile unsigned*)&g_flags[t] < epoch) { }
        }
        __syncthreads();
        if (t == 0) {
            __threadfence();
            *(volatile unsigned*)&g_gen = epoch;     // release
        }
    } else {
        if (threadIdx.x == 0) {
            __threadfence();                          // release my writes
            *(volatile unsigned*)&g_flags[blockIdx.x] = epoch;
            while (*(volatile unsigned*)&g_gen < epoch) { }
        }
    }
    __syncthreads();
    __threadfence();                                  // acquire others' writes
}

__device__ __forceinline__ void group_barrier(int g) {
    asm volatile("bar.sync %0, 128;" :: "r"(1 + g) : "memory");
}

__device__ __forceinline__ float decode_lam(const void* p) {
    int raw = *(const int*)p;
    unsigned ub = (unsigned)raw;
    if (ub < 0x01000000u) return (float)raw;   // small-int bits (int32/int64 low)
    return __int_as_float(raw);                // float32 bits
}

// P1: u = (adj>0 && i!=j) ? exp(-lam*dist) : 0
// P2: W = od/S on S = u + offdiag(u@u)
// P3: out = u .* (W + [W | u^T] @ [u^T ; W])   (single K=768 GEMM)
// 4 warp-groups of 128 threads split K; 4x2 register micro-tile per thread.
__global__ __launch_bounds__(512, 1)
void fused_kernel(const float* __restrict__ od,
                  const int*   __restrict__ adj,
                  const float* __restrict__ dist,
                  const void*  __restrict__ lam_p,
                  float*       __restrict__ out) {
    __shared__ __align__(16) float Asm[4][TS][PA];   // [group][k][row], A^T
    __shared__ __align__(16) float Bsm[4][TS][PB];   // [group][k][col]

    const int tid  = threadIdx.x;
    const int g    = tid >> 7;                 // group 0..3
    const int gtid = tid & 127;
    const int tyy = gtid >> 4;                 // rows 4*tyy..+3
    const int txx = gtid & 15;                 // cols 2*txx..+1
    const int lr = gtid >> 3;                  // load rows lr, lr+16
    const int lq = gtid & 7;                   // load col-quad
    const int tileX = blockIdx.x % NT;
    const int tileY = blockIdx.x / NT;
    const int rowBlk = tileY * TS;
    const int colBlk = tileX * TS;
    float* red = &Asm[0][0][0];                // 16KB reduction scratch (reused)

    // epoch base: pre-launch g_gen (identical for all blocks; see barrier note)
    const unsigned base = *(volatile unsigned*)&g_gen;

    // epilogue output mapping: thread -> 2 consecutive elements
    const int er  = tid >> 4;                  // tile row 0..31
    const int ec0 = 2 * (tid & 15);            // tile col pair
    const int esrc = (((er >> 2) << 4) + (tid & 15)) * 8 + ((er & 3) << 1);

    // ---------------- Phase 1: build u (2 elems/thread) ---------------------
    {
        const float lam = decode_lam(lam_p);
        int bidx = blockIdx.x * 1024 + tid * 2;
        int2   a2 = *(const int2*)&adj[bidx];
        float2 d2 = *(const float2*)&dist[bidx];
        int r = bidx / NN;
        int c = bidx - r * NN;
        float2 v;
        v.x = (a2.x > 0 && r != c    ) ? expf(-lam * d2.x) : 0.f;
        v.y = (a2.y > 0 && r != c + 1) ? expf(-lam * d2.y) : 0.f;
        *(float2*)&g_u[bidx] = v;
    }
    grid_barrier(base + 1);

    // ---------------- Phase 2: G = u@u, W epilogue --------------------------
    {
        float acc[4][2] = {};
        const int tb = g * 3;                  // 3 k-tiles per group
        int p0 = tb * TS;
        float4 aR0 = *(const float4*)&g_u[(rowBlk + lr) * NN + p0 + 4 * lq];
        float4 aR1 = *(const float4*)&g_u[(rowBlk + lr + 16) * NN + p0 + 4 * lq];
        float4 bR0 = *(const float4*)&g_u[(p0 + lr) * NN + colBlk + 4 * lq];
        float4 bR1 = *(const float4*)&g_u[(p0 + lr + 16) * NN + colBlk + 4 * lq];
#pragma unroll 1
        for (int t = 0; t < 3; ++t) {
            Asm[g][4 * lq + 0][lr] = aR0.x;  Asm[g][4 * lq + 0][lr + 16] = aR1.x;
            Asm[g][4 * lq + 1][lr] = aR0.y;  Asm[g][4 * lq + 1][lr + 16] = aR1.y;
            Asm[g][4 * lq + 2][lr] = aR0.z;  Asm[g][4 * lq + 2][lr + 16] = aR1.z;
            Asm[g][4 * lq + 3][lr] = aR0.w;  Asm[g][4 * lq + 3][lr + 16] = aR1.w;
            *(float2*)&Bsm[g][lr][4 * lq]          = make_float2(bR0.x, bR0.y);
            *(float2*)&Bsm[g][lr][4 * lq + 2]      = make_float2(bR0.z, bR0.w);
            *(float2*)&Bsm[g][lr + 16][4 * lq]     = make_float2(bR1.x, bR1.y);
            *(float2*)&Bsm[g][lr + 16][4 * lq + 2] = make_float2(bR1.z, bR1.w);
            group_barrier(g);
            if (t + 1 < 3) {
                int pn = (tb + t + 1) * TS;
                aR0 = *(const float4*)&g_u[(rowBlk + lr) * NN + pn + 4 * lq];
                aR1 = *(const float4*)&g_u[(rowBlk + lr + 16) * NN + pn + 4 * lq];
                bR0 = *(const float4*)&g_u[(pn + lr) * NN + colBlk + 4 * lq];
                bR1 = *(const float4*)&g_u[(pn + lr + 16) * NN + colBlk + 4 * lq];
            }
#pragma unroll
            for (int k = 0; k < TS; ++k) {
                float4 a = *(const float4*)&Asm[g][k][4 * tyy];
                float2 b = *(const float2*)&Bsm[g][k][2 * txx];
                acc[0][0] = fmaf(a.x, b.x, acc[0][0]);
                acc[0][1] = fmaf(a.x, b.y, acc[0][1]);
                acc[1][0] = fmaf(a.y, b.x, acc[1][0]);
                acc[1][1] = fmaf(a.y, b.y, acc[1][1]);
                acc[2][0] = fmaf(a.z, b.x, acc[2][0]);
                acc[2][1] = fmaf(a.z, b.y, acc[2][1]);
                acc[3][0] = fmaf(a.w, b.x, acc[3][0]);
                acc[3][1] = fmaf(a.w, b.y, acc[3][1]);
            }
            group_barrier(g);
        }
        __syncthreads();
        {
            float* dst = &red[tid * 8];
            *(float4*)&dst[0] = make_float4(acc[0][0], acc[0][1], acc[1][0], acc[1][1]);
            *(float4*)&dst[4] = make_float4(acc[2][0], acc[2][1], acc[3][0], acc[3][1]);
        }
        __syncthreads();
        {
            float s0 = 0.f, s1 = 0.f;
#pragma unroll
            for (int gg = 0; gg < 4; ++gg) {
                float2 v = *(const float2*)&red[gg * 1024 + esrc];
                s0 += v.x; s1 += v.y;
            }
            int r = rowBlk + er;
            int c0 = colBlk + ec0;
            int idx = r * NN + c0;
            float2 uv  = *(const float2*)&g_u[idx];
            float2 odv = *(const float2*)&od[idx];
            float S0 = uv.x + ((r != c0)     ? s0 : 0.f);
            float S1 = uv.y + ((r != c0 + 1) ? s1 : 0.f);
            float2 w2;
            w2.x = (odv.x > 0.f && r != c0     && S0 > 0.f) ? (odv.x / S0) : 0.f;
            w2.y = (odv.y > 0.f && r != c0 + 1 && S1 > 0.f) ? (odv.y / S1) : 0.f;
            *(float2*)&g_W[idx] = w2;
        }
    }
    grid_barrier(base + 2);

    // ---------------- Phase 3: C = [W | u^T] @ [u^T ; W] --------------------
    // Groups 0,1: first half (A=W rows, B=u rows of colBlk; transposed stores)
    // Groups 2,3: second half (A=u^T, B=W; natural stores)
    {
        float acc[4][2] = {};
        const int first = (g < 2);
        float4 aR0, aR1, bR0, bR1;
        {
            int vt = g * 6;
            int p0 = first ? vt * TS : (vt - 12) * TS;
            if (first) {
                aR0 = *(const float4*)&g_W[(rowBlk + lr) * NN + p0 + 4 * lq];
                aR1 = *(const float4*)&g_W[(rowBlk + lr + 16) * NN + p0 + 4 * lq];
                bR0 = *(const float4*)&g_u[(colBlk + lr) * NN + p0 + 4 * lq];
                bR1 = *(const float4*)&g_u[(colBlk + lr + 16) * NN + p0 + 4 * lq];
            } else {
                aR0 = *(const float4*)&g_u[(p0 + lr) * NN + rowBlk + 4 * lq];
                aR1 = *(const float4*)&g_u[(p0 + lr + 16) * NN + rowBlk + 4 * lq];
                bR0 = *(const float4*)&g_W[(p0 + lr) * NN + colBlk + 4 * lq];
                bR1 = *(const float4*)&g_W[(p0 + lr + 16) * NN + colBlk + 4 * lq];
            }
        }
#pragma unroll 1
        for (int t = 0; t < 6; ++t) {
            if (first) {
                Asm[g][4 * lq + 0][lr] = aR0.x;  Asm[g][4 * lq + 0][lr + 16] = aR1.x;
                Asm[g][4 * lq + 1][lr] = aR0.y;  Asm[g][4 * lq + 1][lr + 16] = aR1.y;
                Asm[g][4 * lq + 2][lr] = aR0.z;  Asm[g][4 * lq + 2][lr + 16] = aR1.z;
                Asm[g][4 * lq + 3][lr] = aR0.w;  Asm[g][4 * lq + 3][lr + 16] = aR1.w;
                Bsm[g][4 * lq + 0][lr] = bR0.x;  Bsm[g][4 * lq + 0][lr + 16] = bR1.x;
                Bsm[g][4 * lq + 1][lr] = bR0.y;  Bsm[g][4 * lq + 1][lr + 16] = bR1.y;
                Bsm[g][4 * lq + 2][lr] = bR0.z;  Bsm[g][4 * lq + 2][lr + 16] = bR1.z;
                Bsm[g][4 * lq + 3][lr] = bR0.w;  Bsm[g][4 * lq + 3][lr + 16] = bR1.w;
            } else {
                *(float2*)&Asm[g][lr][4 * lq]          = make_float2(aR0.x, aR0.y);
                *(float2*)&Asm[g][lr][4 * lq + 2]      = make_float2(aR0.z, aR0.w);
                *(float2*)&Asm[g][lr + 16][4 * lq]     = make_float2(aR1.x, aR1.y);
                *(float2*)&Asm[g][lr + 16][4 * lq + 2] = make_float2(aR1.z, aR1.w);
                *(float2*)&Bsm[g][lr][4 * lq]          = make_float2(bR0.x, bR0.y);
                *(float2*)&Bsm[g][lr][4 * lq + 2]      = make_float2(bR0.z, bR0.w);
                *(float2*)&Bsm[g][lr + 16][4 * lq]     = make_float2(bR1.x, bR1.y);
                *(float2*)&Bsm[g][lr + 16][4 * lq + 2] = make_float2(bR1.z, bR1.w);
            }
            group_barrier(g);
            if (t + 1 < 6) {
                int vt = g * 6 + t + 1;
                int p0 = first ? vt * TS : (vt - 12) * TS;
                if (first) {
                    aR0 = *(const float4*)&g_W[(rowBlk + lr) * NN + p0 + 4 * lq];
                    aR1 = *(const float4*)&g_W[(rowBlk + lr + 16) * NN + p0 + 4 * lq];
                    bR0 = *(const float4*)&g_u[(colBlk + lr) * NN + p0 + 4 * lq];
                    bR1 = *(const float4*)&g_u[(colBlk + lr + 16) * NN + p0 + 4 * lq];
                } else {
                    aR0 = *(const float4*)&g_u[(p0 + lr) * NN + rowBlk + 4 * lq];
                    aR1 = *(const float4*)&g_u[(p0 + lr + 16) * NN + rowBlk + 4 * lq];
                    bR0 = *(const float4*)&g_W[(p0 + lr) * NN + colBlk + 4 * lq];
                    bR1 = *(const float4*)&g_W[(p0 + lr + 16) * NN + colBlk + 4 * lq];
                }
            }
#pragma unroll
            for (int k = 0; k < TS; ++k) {
                float4 a = *(const float4*)&Asm[g][k][4 * tyy];
                float2 b = *(const float2*)&Bsm[g][k][2 * txx];
                acc[0][0] = fmaf(a.x, b.x, acc[0][0]);
                acc[0][1] = fmaf(a.x, b.y, acc[0][1]);
                acc[1][0] = fmaf(a.y, b.x, acc[1][0]);
                acc[1][1] = fmaf(a.y, b.y, acc[1][1]);
                acc[2][0] = fmaf(a.z, b.x, acc[2][0]);
                acc[2][1] = fmaf(a.z, b.y, acc[2][1]);
                acc[3][0] = fmaf(a.w, b.x, acc[3][0]);
                acc[3][1] = fmaf(a.w, b.y, acc[3][1]);
            }
            group_barrier(g);
        }
        __syncthreads();
        {
            float* dst = &red[tid * 8];
            *(float4*)&dst[0] = make_float4(acc[0][0], acc[0][1], acc[1][0], acc[1][1]);
            *(float4*)&dst[4] = make_float4(acc[2][0], acc[2][1], acc[3][0], acc[3][1]);
        }
        __syncthreads();
        {
            float s0 = 0.f, s1 = 0.f;
#pragma unroll
            for (int gg = 0; gg < 4; ++gg) {
                float2 v = *(const float2*)&red[gg * 1024 + esrc];
                s0 += v.x; s1 += v.y;
            }
            int r = rowBlk + er;
            int c0 = colBlk + ec0;
            int idx = r * NN + c0;
            float2 uv = *(const float2*)&g_u[idx];
            float2 wv = *(const float2*)&g_W[idx];
            float2 o;
            o.x = uv.x * (wv.x + s0);
            o.y = uv.y * (wv.y + s1);
            *(float2*)&out[idx] = o;
        }
    }
}

extern "C" void kernel_launch(void* const* d_in, const int* in_sizes, int n_in,
                              void* d_out, int out_size) {
    const float* od   = (const float*)d_in[0];
    const int*   adj  = (const int*)d_in[1];
    const float* dist = (const float*)d_in[2];
    const void*  lamp = d_in[3];
    float* out = (float*)d_out;

    fused_kernel<<<NBLK, 512>>>(od, adj, dist, lamp, out);
}